// round 4
// baseline (speedup 1.0000x reference)
#include <cuda_runtime.h>
#include <cuda_bf16.h>
#include <cstdint>

// Problem constants (fixed by the reference generator)
#define N_NODES 50000
#define IN_DIM  1000
#define HIDDEN  256
#define OUT_DIM 2
#define MAX_ENTRIES 1700000   // E (1.6M) + self loops (50k) with slack

// ---------------- scratch (static device allocations; no runtime alloc) -------------
__device__ __align__(16) float g_h1[N_NODES * HIDDEN];      // x @ W1
__device__ __align__(16) float g_hrelu[N_NODES * HIDDEN];   // relu(agg1 + b1)
__device__ __align__(16) float g_h2[N_NODES * OUT_DIM];     // hrelu @ W2
__device__ int   g_deg[N_NODES];
__device__ int   g_off[N_NODES + 1];
__device__ int   g_cursor[N_NODES];
__device__ float g_dinv[N_NODES];
__device__ int   g_csr_src[MAX_ENTRIES];
__device__ float g_csr_norm[MAX_ENTRIES];
__device__ int   g_is64;     // 1 if edge_index buffer is int64, 0 if int32

// ---------------- -1: detect edge_index dtype (int32 vs int64) ----------------
// Reads only the first 3.2M int32 words (12.8 MB), which is within the buffer
// under EITHER interpretation. If the data is little-endian int64 with values
// in [0, 50000), every odd-index 32-bit word is a zero high-half. If int32,
// odd words are uniform edge indices — the chance 32768 samples are all zero
// is ~(2e-5)^32768 ≈ 0.
__global__ void k_detect(const int* __restrict__ ei32, int n_words) {
    __shared__ int nz;
    if (threadIdx.x == 0) nz = 0;
    __syncthreads();
    for (int i = threadIdx.x; i < 32768; i += blockDim.x) {
        int w = 1 + 96 * i;               // odd indices spread across the buffer
        if (w < n_words && ei32[w] != 0) nz = 1;
    }
    __syncthreads();
    if (threadIdx.x == 0) g_is64 = (nz == 0) ? 1 : 0;
}

__device__ __forceinline__ int load_edge(const void* ei, int pos) {
    int v;
    if (g_is64) v = (int)((const long long*)ei)[pos];
    else        v = ((const int*)ei)[pos];
    // clamp: guarantees no OOB trap even on unexpected data
    return min(max(v, 0), N_NODES - 1);
}

// ---------------- 0: init deg to 1 (self loop) ----------------
__global__ void k_init_deg() {
    int n = blockIdx.x * blockDim.x + threadIdx.x;
    if (n < N_NODES) g_deg[n] = 1;
}

// ---------------- 1: degree histogram over dst ----------------
__global__ void k_hist(const void* __restrict__ ei, int E) {
    int e = blockIdx.x * blockDim.x + threadIdx.x;
    if (e < E) {
        int d = load_edge(ei, E + e);
        atomicAdd(&g_deg[d], 1);
    }
}

// ---------------- 2: exclusive scan (single block), dinv, cursor ----------------
__global__ void k_scan() {
    __shared__ int sh[1024];
    int t = threadIdx.x;
    int carry = 0;
    for (int base = 0; base < N_NODES; base += 1024) {
        int i = base + t;
        int v = (i < N_NODES) ? g_deg[i] : 0;
        sh[t] = v;
        __syncthreads();
        #pragma unroll
        for (int offs = 1; offs < 1024; offs <<= 1) {
            int add = (t >= offs) ? sh[t - offs] : 0;
            __syncthreads();
            sh[t] += add;
            __syncthreads();
        }
        int incl  = sh[t];
        int total = sh[1023];
        __syncthreads();           // all reads of sh done before next iter writes
        if (i < N_NODES) {
            int excl = carry + incl - v;
            g_off[i]    = excl;
            g_cursor[i] = excl;
            g_dinv[i]   = rsqrtf((float)v);
        }
        carry += total;
    }
    if (t == 0) g_off[N_NODES] = carry;
}

// ---------------- 3: fill CSR (edges + self loops) ----------------
__global__ void k_fill(const void* __restrict__ ei, int E) {
    int idx = blockIdx.x * blockDim.x + threadIdx.x;
    int total = E + N_NODES;
    if (idx >= total) return;
    int s, d;
    if (idx < E) { s = load_edge(ei, idx); d = load_edge(ei, E + idx); }
    else         { s = d = idx - E; }
    int pos = atomicAdd(&g_cursor[d], 1);
    if (pos < MAX_ENTRIES) {
        g_csr_src[pos]  = s;
        g_csr_norm[pos] = g_dinv[s] * g_dinv[d];
    }
}

// ---------------- 4: GEMM1  h1 = x @ W1   (fp32 SIMT, 128x64x8 tiles) ----------------
#define BM 128
#define BN 64
#define BK 8
#define TM 8
#define TN 4
__global__ __launch_bounds__(256, 2) void k_gemm1(const float* __restrict__ x,
                                                  const float* __restrict__ W1) {
    __shared__ __align__(16) float As[BK][BM];
    __shared__ __align__(16) float Bs[BK][BN];
    const int bm0 = blockIdx.x * BM;
    const int bn0 = blockIdx.y * BN;
    const int t  = threadIdx.x;
    const int tx = t & 15;       // 0..15 -> 4 cols each
    const int ty = t >> 4;       // 0..15 -> 8 rows each

    // A-load mapping: one float4 per thread
    const int ar = t >> 1;           // 0..127 tile row
    const int ac = (t & 1) * 4;      // 0 or 4 (k within tile)
    const int arow = bm0 + ar;
    // B-load mapping: one float2 per thread
    const int bk = t >> 5;           // 0..7
    const int bc = (t & 31) * 2;     // 0..62

    float acc[TM][TN];
    #pragma unroll
    for (int i = 0; i < TM; i++)
        #pragma unroll
        for (int j = 0; j < TN; j++) acc[i][j] = 0.f;

    for (int k0 = 0; k0 < IN_DIM; k0 += BK) {
        float4 av = make_float4(0.f, 0.f, 0.f, 0.f);
        if (arow < N_NODES)
            av = *(const float4*)&x[arow * IN_DIM + k0 + ac];
        As[ac + 0][ar] = av.x;
        As[ac + 1][ar] = av.y;
        As[ac + 2][ar] = av.z;
        As[ac + 3][ar] = av.w;
        float2 bv = *(const float2*)&W1[(k0 + bk) * HIDDEN + bn0 + bc];
        Bs[bk][bc]     = bv.x;
        Bs[bk][bc + 1] = bv.y;
        __syncthreads();
        #pragma unroll
        for (int k = 0; k < BK; k++) {
            float4 a0 = *(const float4*)&As[k][ty * TM];
            float4 a1 = *(const float4*)&As[k][ty * TM + 4];
            float4 b  = *(const float4*)&Bs[k][tx * TN];
            float ra[TM] = {a0.x, a0.y, a0.z, a0.w, a1.x, a1.y, a1.z, a1.w};
            float rb[TN] = {b.x, b.y, b.z, b.w};
            #pragma unroll
            for (int i = 0; i < TM; i++)
                #pragma unroll
                for (int j = 0; j < TN; j++)
                    acc[i][j] = fmaf(ra[i], rb[j], acc[i][j]);
        }
        __syncthreads();
    }

    #pragma unroll
    for (int i = 0; i < TM; i++) {
        int m = bm0 + ty * TM + i;
        if (m < N_NODES) {
            float4 v = make_float4(acc[i][0], acc[i][1], acc[i][2], acc[i][3]);
            *(float4*)&g_h1[m * HIDDEN + bn0 + tx * TN] = v;
        }
    }
}

// ---------------- 5: aggregation 1 + bias + relu (atomic-free gather) ----------------
__global__ __launch_bounds__(256) void k_agg1(const float* __restrict__ b1) {
    const int n = blockIdx.x;
    const int t = threadIdx.x;  // 256 threads = one feature each
    const int beg = g_off[n];
    const int end = g_off[n + 1];
    float acc = b1[t];
    __shared__ int   s_src[128];
    __shared__ float s_norm[128];
    const int*   __restrict__ csr_src  = g_csr_src;
    const float* __restrict__ csr_norm = g_csr_norm;
    const float* __restrict__ h1       = g_h1;
    for (int base = beg; base < end; base += 128) {
        int cnt = min(128, end - base);
        if (t < cnt) {
            s_src[t]  = csr_src[base + t];
            s_norm[t] = csr_norm[base + t];
        }
        __syncthreads();
        #pragma unroll 4
        for (int i = 0; i < cnt; i++)
            acc = fmaf(h1[s_src[i] * HIDDEN + t], s_norm[i], acc);
        __syncthreads();
    }
    g_hrelu[n * HIDDEN + t] = fmaxf(acc, 0.f);
}

// ---------------- 6: GEMM2  h2 = hrelu @ W2   (warp per node) ----------------
__global__ __launch_bounds__(256) void k_gemm2(const float* __restrict__ W2) {
    int warp = (blockIdx.x * blockDim.x + threadIdx.x) >> 5;
    int lane = threadIdx.x & 31;
    if (warp >= N_NODES) return;
    const float* __restrict__ hrow = &g_hrelu[warp * HIDDEN];
    float a0 = 0.f, a1 = 0.f;
    #pragma unroll
    for (int j = 0; j < HIDDEN / 32; j++) {
        int k = lane + j * 32;          // coalesced
        float h = hrow[k];
        float2 w = *(const float2*)&W2[k * 2];
        a0 = fmaf(h, w.x, a0);
        a1 = fmaf(h, w.y, a1);
    }
    #pragma unroll
    for (int o = 16; o; o >>= 1) {
        a0 += __shfl_xor_sync(0xffffffffu, a0, o);
        a1 += __shfl_xor_sync(0xffffffffu, a1, o);
    }
    if (lane == 0) *(float2*)&g_h2[warp * 2] = make_float2(a0, a1);
}

// ---------------- 7: aggregation 2 + bias -> output ----------------
__global__ __launch_bounds__(256) void k_agg2(const float* __restrict__ b2,
                                              float* __restrict__ out) {
    int warp = (blockIdx.x * blockDim.x + threadIdx.x) >> 5;
    int lane = threadIdx.x & 31;
    if (warp >= N_NODES) return;
    int beg = g_off[warp];
    int end = g_off[warp + 1];
    const int*   __restrict__ csr_src  = g_csr_src;
    const float* __restrict__ csr_norm = g_csr_norm;
    const float* __restrict__ h2       = g_h2;
    float a0 = 0.f, a1 = 0.f;
    for (int i = beg + lane; i < end; i += 32) {
        int s    = csr_src[i];
        float nm = csr_norm[i];
        float2 v = *(const float2*)&h2[s * 2];
        a0 = fmaf(v.x, nm, a0);
        a1 = fmaf(v.y, nm, a1);
    }
    #pragma unroll
    for (int o = 16; o; o >>= 1) {
        a0 += __shfl_xor_sync(0xffffffffu, a0, o);
        a1 += __shfl_xor_sync(0xffffffffu, a1, o);
    }
    if (lane == 0) {
        out[warp * 2 + 0] = a0 + b2[0];
        out[warp * 2 + 1] = a1 + b2[1];
    }
}

// ---------------- launch ----------------
extern "C" void kernel_launch(void* const* d_in, const int* in_sizes, int n_in,
                              void* d_out, int out_size) {
    // Identify inputs by element count — robust to metadata ordering.
    // x: 50,000,000 | W1: 256,000 | b1: 256 | W2: 512 | b2: 2 | edge_index: 3,200,000
    const float* x   = nullptr;
    const float* W1  = nullptr;
    const float* b1  = nullptr;
    const float* W2  = nullptr;
    const float* b2  = nullptr;
    const void*  ei  = nullptr;
    int ei_elems = 0;
    for (int i = 0; i < n_in; i++) {
        switch (in_sizes[i]) {
            case 50000000: x  = (const float*)d_in[i]; break;
            case 256000:   W1 = (const float*)d_in[i]; break;
            case 256:      b1 = (const float*)d_in[i]; break;
            case 512:      W2 = (const float*)d_in[i]; break;
            case 2:        b2 = (const float*)d_in[i]; break;
            case 3200000:  ei = d_in[i]; ei_elems = in_sizes[i]; break;
            default: break;
        }
    }
    float* out = (float*)d_out;
    const int E = ei_elems / 2;   // 1.6M regardless of int32/int64 storage

    // dtype detection + CSR build
    k_detect<<<1, 256>>>((const int*)ei, ei_elems);
    k_init_deg<<<(N_NODES + 255) / 256, 256>>>();
    k_hist<<<(E + 255) / 256, 256>>>(ei, E);
    k_scan<<<1, 1024>>>();
    k_fill<<<(E + N_NODES + 255) / 256, 256>>>(ei, E);

    // Layer 1
    dim3 g1((N_NODES + BM - 1) / BM, HIDDEN / BN);
    k_gemm1<<<g1, 256>>>(x, W1);
    k_agg1<<<N_NODES, 256>>>(b1);

    // Layer 2
    int warps_blocks = (N_NODES * 32 + 255) / 256;
    k_gemm2<<<warps_blocks, 256>>>(W2);
    k_agg2<<<warps_blocks, 256>>>(b2, out);
}

// round 5
// speedup vs baseline: 1.8099x; 1.8099x over previous
#include <cuda_runtime.h>
#include <cuda_bf16.h>
#include <cstdint>

#define N_NODES 50000
#define IN_DIM  1000
#define HIDDEN  256
#define OUT_DIM 2
#define MAX_ENTRIES 1700000

// ---------------- scratch ----------------
__device__ __align__(16) float g_h1[N_NODES * HIDDEN];
__device__ __align__(16) float g_hrelu[N_NODES * HIDDEN];
__device__ __align__(16) float g_h2[N_NODES * OUT_DIM];
__device__ int   g_deg[N_NODES];
__device__ int   g_off[N_NODES + 1];
__device__ int   g_cursor[N_NODES];
__device__ float g_dinv[N_NODES];
__device__ int   g_csr_src[MAX_ENTRIES];
__device__ float g_csr_norm[MAX_ENTRIES];
__device__ int   g_is64;
__device__ int   g_bsum[64];

// ---------------- dtype detect (int32 vs int64 edge buffer) ----------------
__global__ void k_detect(const int* __restrict__ ei32, int n_words) {
    __shared__ int nz;
    if (threadIdx.x == 0) nz = 0;
    __syncthreads();
    for (int i = threadIdx.x; i < 32768; i += blockDim.x) {
        int w = 1 + 96 * i;
        if (w < n_words && ei32[w] != 0) nz = 1;
    }
    __syncthreads();
    if (threadIdx.x == 0) g_is64 = (nz == 0) ? 1 : 0;
}

__device__ __forceinline__ int load_edge(const void* ei, int pos) {
    int v;
    if (g_is64) v = (int)((const long long*)ei)[pos];
    else        v = ((const int*)ei)[pos];
    return min(max(v, 0), N_NODES - 1);
}

// ---------------- CSR build ----------------
__global__ void k_init_deg() {
    int n = blockIdx.x * blockDim.x + threadIdx.x;
    if (n < N_NODES) g_deg[n] = 1;
}

__global__ void k_hist(const void* __restrict__ ei, int E) {
    int e = blockIdx.x * blockDim.x + threadIdx.x;
    if (e < E) atomicAdd(&g_deg[load_edge(ei, E + e)], 1);
}

// parallel scan, stage 1: per-block local exclusive scan + block sums + dinv
__global__ void k_s1() {
    __shared__ int sh[1024];
    int t = threadIdx.x;
    int i = blockIdx.x * 1024 + t;
    int v = (i < N_NODES) ? g_deg[i] : 0;
    sh[t] = v;
    __syncthreads();
    #pragma unroll
    for (int offs = 1; offs < 1024; offs <<= 1) {
        int add = (t >= offs) ? sh[t - offs] : 0;
        __syncthreads();
        sh[t] += add;
        __syncthreads();
    }
    if (i < N_NODES) {
        g_off[i]  = sh[t] - v;      // local exclusive
        g_dinv[i] = rsqrtf((float)v);
    }
    if (t == 1023) g_bsum[blockIdx.x] = sh[1023];
}

// stage 2: serial scan of block sums (49 values)
__global__ void k_s2(int nblocks) {
    if (threadIdx.x == 0) {
        int acc = 0;
        for (int b = 0; b < nblocks; b++) {
            int v = g_bsum[b];
            g_bsum[b] = acc;
            acc += v;
        }
        g_off[N_NODES] = acc;
    }
}

// stage 3: add carries, init cursor
__global__ void k_s3() {
    int i = blockIdx.x * 1024 + threadIdx.x;
    if (i < N_NODES) {
        int o = g_off[i] + g_bsum[blockIdx.x];
        g_off[i]    = o;
        g_cursor[i] = o;
    }
}

__global__ void k_fill(const void* __restrict__ ei, int E) {
    int idx = blockIdx.x * blockDim.x + threadIdx.x;
    int total = E + N_NODES;
    if (idx >= total) return;
    int s, d;
    if (idx < E) { s = load_edge(ei, idx); d = load_edge(ei, E + idx); }
    else         { s = d = idx - E; }
    int pos = atomicAdd(&g_cursor[d], 1);
    if (pos < MAX_ENTRIES) {
        g_csr_src[pos]  = s;
        g_csr_norm[pos] = g_dinv[s] * g_dinv[d];
    }
}

// ---------------- GEMM1: h1 = x @ W1, TF32 mma.sync ----------------
// 128x128x16 block tile, 256 threads = 8 warps as 4(M) x 2(N); warp: 32x64.
#define PADA 28     // word stride of As row (conflict-free frag loads)
#define PADB 136    // word stride of Bs row

__device__ __forceinline__ uint32_t f2tf32(float v) {
    uint32_t u;
    asm("cvt.rna.tf32.f32 %0, %1;" : "=r"(u) : "f"(v));
    return u;
}

__global__ __launch_bounds__(256, 2) void k_gemm1(const float* __restrict__ x,
                                                  const float* __restrict__ W1) {
    __shared__ uint32_t As[128 * PADA];
    __shared__ uint32_t Bs[16 * PADB];

    const int t    = threadIdx.x;
    const int lane = t & 31;
    const int wid  = t >> 5;
    const int wm   = wid & 3;          // warp m index (0..3) -> 32 rows
    const int wn   = wid >> 2;         // warp n index (0..1) -> 64 cols
    const int g    = lane >> 2;        // groupID
    const int tig  = lane & 3;         // thread in group

    const int bm0 = blockIdx.x * 128;
    const int bn0 = blockIdx.y * 128;

    // A staging: 2 float4 per thread. rowA in tile, colA = quad*4
    const int rowA0 = t >> 2;          // 0..63
    const int quadA = t & 3;
    // B staging: 2 float4 per thread. rowB = k row, colB = cq*4
    const int rowB0 = t >> 5;          // 0..7
    const int cqB   = t & 31;

    float acc[2][8][4];
    #pragma unroll
    for (int mt = 0; mt < 2; mt++)
        #pragma unroll
        for (int nt = 0; nt < 8; nt++)
            #pragma unroll
            for (int r = 0; r < 4; r++) acc[mt][nt][r] = 0.f;

    float4 a_st[2], b_st[2];

    // prologue load (k0 = 0)
    {
        #pragma unroll
        for (int i = 0; i < 2; i++) {
            int gr = bm0 + rowA0 + i * 64;
            a_st[i] = (gr < N_NODES)
                ? *(const float4*)&x[(long long)gr * IN_DIM + quadA * 4]
                : make_float4(0.f, 0.f, 0.f, 0.f);
            int kb = rowB0 + i * 8;
            b_st[i] = *(const float4*)&W1[kb * HIDDEN + bn0 + cqB * 4];
        }
    }

    const int NITER = (IN_DIM + 15) / 16;   // 63 (last iter half-tail)
    for (int it = 0; it < NITER; it++) {
        int k0 = it * 16;
        __syncthreads();   // prev compute done, smem reusable
        // store stage -> smem (tf32 RNA convert)
        #pragma unroll
        for (int i = 0; i < 2; i++) {
            int r = rowA0 + i * 64;
            bool ok = (k0 + quadA * 4) < IN_DIM;
            uint32_t* p = &As[r * PADA + quadA * 4];
            p[0] = ok ? f2tf32(a_st[i].x) : 0u;
            p[1] = ok ? f2tf32(a_st[i].y) : 0u;
            p[2] = ok ? f2tf32(a_st[i].z) : 0u;
            p[3] = ok ? f2tf32(a_st[i].w) : 0u;
            int kb = rowB0 + i * 8;
            bool okb = (k0 + kb) < IN_DIM;
            uint32_t* q = &Bs[kb * PADB + cqB * 4];
            q[0] = okb ? f2tf32(b_st[i].x) : 0u;
            q[1] = okb ? f2tf32(b_st[i].y) : 0u;
            q[2] = okb ? f2tf32(b_st[i].z) : 0u;
            q[3] = okb ? f2tf32(b_st[i].w) : 0u;
        }
        __syncthreads();
        // prefetch next tile into regs (overlaps with compute below)
        if (it + 1 < NITER) {
            int kn = k0 + 16;
            #pragma unroll
            for (int i = 0; i < 2; i++) {
                int gr = bm0 + rowA0 + i * 64;
                bool okc = (kn + quadA * 4) < IN_DIM;
                a_st[i] = (gr < N_NODES && okc)
                    ? *(const float4*)&x[(long long)gr * IN_DIM + kn + quadA * 4]
                    : make_float4(0.f, 0.f, 0.f, 0.f);
                int kb = kn + rowB0 + i * 8;
                b_st[i] = (kb < IN_DIM)
                    ? *(const float4*)&W1[kb * HIDDEN + bn0 + cqB * 4]
                    : make_float4(0.f, 0.f, 0.f, 0.f);
            }
        }
        // compute: 2 k8-steps
        #pragma unroll
        for (int ks = 0; ks < 2; ks++) {
            uint32_t af[2][4], bf[8][2];
            #pragma unroll
            for (int mt = 0; mt < 2; mt++) {
                int r0 = wm * 32 + mt * 16 + g;
                int c0 = ks * 8 + tig;
                af[mt][0] = As[r0 * PADA + c0];
                af[mt][1] = As[(r0 + 8) * PADA + c0];
                af[mt][2] = As[r0 * PADA + c0 + 4];
                af[mt][3] = As[(r0 + 8) * PADA + c0 + 4];
            }
            #pragma unroll
            for (int nt = 0; nt < 8; nt++) {
                int kk = ks * 8 + tig;
                int nn = wn * 64 + nt * 8 + g;
                bf[nt][0] = Bs[kk * PADB + nn];
                bf[nt][1] = Bs[(kk + 4) * PADB + nn];
            }
            #pragma unroll
            for (int mt = 0; mt < 2; mt++)
                #pragma unroll
                for (int nt = 0; nt < 8; nt++) {
                    asm volatile(
                        "mma.sync.aligned.m16n8k8.row.col.f32.tf32.tf32.f32 "
                        "{%0,%1,%2,%3}, {%4,%5,%6,%7}, {%8,%9}, {%0,%1,%2,%3};"
                        : "+f"(acc[mt][nt][0]), "+f"(acc[mt][nt][1]),
                          "+f"(acc[mt][nt][2]), "+f"(acc[mt][nt][3])
                        : "r"(af[mt][0]), "r"(af[mt][1]), "r"(af[mt][2]), "r"(af[mt][3]),
                          "r"(bf[nt][0]), "r"(bf[nt][1]));
                }
        }
    }

    // epilogue: c0,c1 -> (row g, col 2*tig), c2,c3 -> (row g+8)
    #pragma unroll
    for (int mt = 0; mt < 2; mt++) {
        #pragma unroll
        for (int nt = 0; nt < 8; nt++) {
            int col = bn0 + wn * 64 + nt * 8 + 2 * tig;
            int r0  = bm0 + wm * 32 + mt * 16 + g;
            if (r0 < N_NODES)
                *(float2*)&g_h1[(long long)r0 * HIDDEN + col] =
                    make_float2(acc[mt][nt][0], acc[mt][nt][1]);
            int r1 = r0 + 8;
            if (r1 < N_NODES)
                *(float2*)&g_h1[(long long)r1 * HIDDEN + col] =
                    make_float2(acc[mt][nt][2], acc[mt][nt][3]);
        }
    }
}

// ---------------- agg1 + bias + relu ----------------
__global__ __launch_bounds__(256) void k_agg1(const float* __restrict__ b1) {
    const int n = blockIdx.x;
    const int t = threadIdx.x;
    const int beg = g_off[n];
    const int end = g_off[n + 1];
    float acc = b1[t];
    __shared__ int   s_src[128];
    __shared__ float s_norm[128];
    const int*   __restrict__ csr_src  = g_csr_src;
    const float* __restrict__ csr_norm = g_csr_norm;
    const float* __restrict__ h1       = g_h1;
    for (int base = beg; base < end; base += 128) {
        int cnt = min(128, end - base);
        if (t < cnt) {
            s_src[t]  = csr_src[base + t];
            s_norm[t] = csr_norm[base + t];
        }
        __syncthreads();
        #pragma unroll 4
        for (int i = 0; i < cnt; i++)
            acc = fmaf(h1[s_src[i] * HIDDEN + t], s_norm[i], acc);
        __syncthreads();
    }
    g_hrelu[n * HIDDEN + t] = fmaxf(acc, 0.f);
}

// ---------------- gemm2: warp per node ----------------
__global__ __launch_bounds__(256) void k_gemm2(const float* __restrict__ W2) {
    int warp = (blockIdx.x * blockDim.x + threadIdx.x) >> 5;
    int lane = threadIdx.x & 31;
    if (warp >= N_NODES) return;
    const float* __restrict__ hrow = &g_hrelu[warp * HIDDEN];
    float a0 = 0.f, a1 = 0.f;
    #pragma unroll
    for (int j = 0; j < HIDDEN / 32; j++) {
        int k = lane + j * 32;
        float h = hrow[k];
        float2 w = *(const float2*)&W2[k * 2];
        a0 = fmaf(h, w.x, a0);
        a1 = fmaf(h, w.y, a1);
    }
    #pragma unroll
    for (int o = 16; o; o >>= 1) {
        a0 += __shfl_xor_sync(0xffffffffu, a0, o);
        a1 += __shfl_xor_sync(0xffffffffu, a1, o);
    }
    if (lane == 0) *(float2*)&g_h2[warp * 2] = make_float2(a0, a1);
}

// ---------------- agg2 + bias -> out ----------------
__global__ __launch_bounds__(256) void k_agg2(const float* __restrict__ b2,
                                              float* __restrict__ out) {
    int warp = (blockIdx.x * blockDim.x + threadIdx.x) >> 5;
    int lane = threadIdx.x & 31;
    if (warp >= N_NODES) return;
    int beg = g_off[warp];
    int end = g_off[warp + 1];
    const int*   __restrict__ csr_src  = g_csr_src;
    const float* __restrict__ csr_norm = g_csr_norm;
    const float* __restrict__ h2       = g_h2;
    float a0 = 0.f, a1 = 0.f;
    for (int i = beg + lane; i < end; i += 32) {
        int s    = csr_src[i];
        float nm = csr_norm[i];
        float2 v = *(const float2*)&h2[s * 2];
        a0 = fmaf(v.x, nm, a0);
        a1 = fmaf(v.y, nm, a1);
    }
    #pragma unroll
    for (int o = 16; o; o >>= 1) {
        a0 += __shfl_xor_sync(0xffffffffu, a0, o);
        a1 += __shfl_xor_sync(0xffffffffu, a1, o);
    }
    if (lane == 0) {
        out[warp * 2 + 0] = a0 + b2[0];
        out[warp * 2 + 1] = a1 + b2[1];
    }
}

// ---------------- launch ----------------
extern "C" void kernel_launch(void* const* d_in, const int* in_sizes, int n_in,
                              void* d_out, int out_size) {
    const float* x   = nullptr;
    const float* W1  = nullptr;
    const float* b1  = nullptr;
    const float* W2  = nullptr;
    const float* b2  = nullptr;
    const void*  ei  = nullptr;
    int ei_elems = 0;
    for (int i = 0; i < n_in; i++) {
        switch (in_sizes[i]) {
            case 50000000: x  = (const float*)d_in[i]; break;
            case 256000:   W1 = (const float*)d_in[i]; break;
            case 256:      b1 = (const float*)d_in[i]; break;
            case 512:      W2 = (const float*)d_in[i]; break;
            case 2:        b2 = (const float*)d_in[i]; break;
            case 3200000:  ei = d_in[i]; ei_elems = in_sizes[i]; break;
            default: break;
        }
    }
    float* out = (float*)d_out;
    const int E = ei_elems / 2;
    const int SCAN_BLOCKS = (N_NODES + 1023) / 1024;

    k_detect<<<1, 256>>>((const int*)ei, ei_elems);
    k_init_deg<<<(N_NODES + 255) / 256, 256>>>();
    k_hist<<<(E + 255) / 256, 256>>>(ei, E);
    k_s1<<<SCAN_BLOCKS, 1024>>>();
    k_s2<<<1, 32>>>(SCAN_BLOCKS);
    k_s3<<<SCAN_BLOCKS, 1024>>>();
    k_fill<<<(E + N_NODES + 255) / 256, 256>>>(ei, E);

    dim3 g1((N_NODES + 127) / 128, HIDDEN / 128);
    k_gemm1<<<g1, 256>>>(x, W1);
    k_agg1<<<N_NODES, 256>>>(b1);

    int warps_blocks = (N_NODES * 32 + 255) / 256;
    k_gemm2<<<warps_blocks, 256>>>(W2);
    k_agg2<<<warps_blocks, 256>>>(b2, out);
}